// round 1
// baseline (speedup 1.0000x reference)
#include <cuda_runtime.h>
#include <cuda_bf16.h>
#include <math.h>

// Problem constants
#define BATCH 64
#define FRAMES 128
#define N_IN 512
#define N_HID 2048
#define ALPHA 0.5f
#define DECAY 0.5f
#define THR 0.5f

// mems: [2][64][129][2048], spikes same, concatenated (mems first).
#define MEMS_ELEMS ((size_t)2 * BATCH * (FRAMES + 1) * N_HID)

// Scratch: feedforward drive U[layer][b*FRAMES+t][h]
__device__ float g_U[2][(size_t)BATCH * FRAMES][N_HID];

// ---------------------------------------------------------------------------
// Feedforward GEMM: U[l] = x @ W_l + b_l
// x: [8192, 512] row-major, W: [512, 2048] row-major.
// Classic 128x128 tile, 256 threads, 8x8 per thread, K chunks of 16.
// ---------------------------------------------------------------------------
__global__ void __launch_bounds__(256) ff_kernel(
    const float* __restrict__ x,
    const float* __restrict__ W1, const float* __restrict__ b1,
    const float* __restrict__ W2, const float* __restrict__ b2)
{
    const int layer = blockIdx.z;
    const float* __restrict__ W = layer ? W2 : W1;
    const float* __restrict__ bias = layer ? b2 : b1;
    const int m0 = blockIdx.y * 128;
    const int n0 = blockIdx.x * 128;

    __shared__ float xs[16][128];   // [k][m]
    __shared__ float ws[16][128];   // [k][n]

    const int tid = threadIdx.x;
    const int tx = tid & 15;   // n dim
    const int ty = tid >> 4;   // m dim

    float acc[8][8];
#pragma unroll
    for (int i = 0; i < 8; i++)
#pragma unroll
        for (int j = 0; j < 8; j++) acc[i][j] = 0.f;

    for (int k0 = 0; k0 < N_IN; k0 += 16) {
        // load x tile (128 rows x 16 cols) transposed into xs[k][m]
#pragma unroll
        for (int i = 0; i < 2; i++) {
            int idx = tid + i * 256;         // 0..511
            int row = idx >> 2;              // 0..127
            int c4  = idx & 3;               // 0..3
            float4 v = *(const float4*)&x[(size_t)(m0 + row) * N_IN + k0 + c4 * 4];
            xs[c4 * 4 + 0][row] = v.x;
            xs[c4 * 4 + 1][row] = v.y;
            xs[c4 * 4 + 2][row] = v.z;
            xs[c4 * 4 + 3][row] = v.w;
        }
        // load W tile (16 rows x 128 cols)
#pragma unroll
        for (int i = 0; i < 2; i++) {
            int idx = tid + i * 256;         // 0..511
            int row = idx >> 5;              // 0..15
            int c4  = idx & 31;              // 0..31
            float4 v = *(const float4*)&W[(size_t)(k0 + row) * N_HID + n0 + c4 * 4];
            *(float4*)&ws[row][c4 * 4] = v;
        }
        __syncthreads();

#pragma unroll
        for (int k = 0; k < 16; k++) {
            float a[8], bb[8];
            *(float4*)&a[0] = *(const float4*)&xs[k][ty * 4];
            *(float4*)&a[4] = *(const float4*)&xs[k][ty * 4 + 64];
            *(float4*)&bb[0] = *(const float4*)&ws[k][tx * 4];
            *(float4*)&bb[4] = *(const float4*)&ws[k][tx * 4 + 64];
#pragma unroll
            for (int i = 0; i < 8; i++)
#pragma unroll
                for (int j = 0; j < 8; j++)
                    acc[i][j] = fmaf(a[i], bb[j], acc[i][j]);
        }
        __syncthreads();
    }

    // epilogue: add bias, write U
    float* __restrict__ U = &g_U[layer][0][0];
#pragma unroll
    for (int i = 0; i < 8; i++) {
        int m = m0 + ty * 4 + (i & 3) + (i >> 2) * 64;
#pragma unroll
        for (int j = 0; j < 8; j++) {
            int n = n0 + tx * 4 + (j & 3) + (j >> 2) * 64;
            U[(size_t)m * N_HID + n] = acc[i][j] + bias[n];
        }
    }
}

// ---------------------------------------------------------------------------
// Init: mems[l][b][0][:] = mem0_l, spikes[l][b][0][:] = 0
// ---------------------------------------------------------------------------
__global__ void init_kernel(const float* __restrict__ mem0_1,
                            const float* __restrict__ mem0_2,
                            float* __restrict__ out)
{
    float* mems = out;
    float* spikes = out + MEMS_ELEMS;
    size_t idx = (size_t)blockIdx.x * blockDim.x + threadIdx.x;
    size_t total = (size_t)2 * BATCH * N_HID;
    if (idx >= total) return;
    int l = (int)(idx / ((size_t)BATCH * N_HID));
    size_t rem = idx % ((size_t)BATCH * N_HID);
    int b = (int)(rem / N_HID);
    int h = (int)(rem % N_HID);
    const float* m0 = l ? mem0_2 : mem0_1;
    size_t o = ((size_t)(l * BATCH + b) * (FRAMES + 1) + 0) * N_HID + h;
    mems[o] = m0[(size_t)b * N_HID + h];
    spikes[o] = 0.f;
}

// ---------------------------------------------------------------------------
// One timestep: for each (layer, b, h):
//   y = tanh(0.5*(s_t @ A) + 0.5*U[t]);  m_{t+1} = 0.5*m_t - 0.5*(1-s_t) + y
//   s_{t+1} = (m_{t+1} > 0.5)
// Reads state from out[..][t], writes out[..][t+1].
// Grid: 128 CTAs = 2 layers x 64 column tiles of 32. Block: 256 threads.
// Warp w handles batch rows [w*8, w*8+8), lane = column within tile.
// ---------------------------------------------------------------------------
__global__ void __launch_bounds__(256) step_kernel(
    const float* __restrict__ A1, const float* __restrict__ A2,
    float* __restrict__ out, int t)
{
    const int bx = blockIdx.x;
    const int layer = bx >> 6;
    const int h0 = (bx & 63) * 32;
    const float* __restrict__ A = layer ? A2 : A1;

    __shared__ float As[64][32];       // [k][h] slice
    __shared__ float Ss[64][68];       // [b][k] slice (padded stride)

    const int tid = threadIdx.x;
    const int lane = tid & 31;
    const int w = tid >> 5;
    const int b0 = w * 8;

    float* mems = out;
    float* spikes = out + MEMS_ELEMS;

    float acc[8];
#pragma unroll
    for (int j = 0; j < 8; j++) acc[j] = 0.f;

    for (int k0 = 0; k0 < N_HID; k0 += 64) {
        // stage A: 64 rows x 32 cols. Warp w loads rows w*8 .. w*8+7, coalesced.
#pragma unroll
        for (int i = 0; i < 8; i++) {
            int r = w * 8 + i;
            As[r][lane] = A[(size_t)(k0 + r) * N_HID + h0 + lane];
        }
        // stage spikes: 64 b-rows x 64 k each; 4 threads per row, 4 float4 each
        {
            int b = tid >> 2;
            int q = tid & 3;
            const float* srow =
                spikes + ((size_t)(layer * BATCH + b) * (FRAMES + 1) + t) * N_HID + k0;
#pragma unroll
            for (int i = 0; i < 4; i++) {
                int c4 = q + i * 4;             // 0..15
                float4 v = *(const float4*)&srow[c4 * 4];
                *(float4*)&Ss[b][c4 * 4] = v;
            }
        }
        __syncthreads();

#pragma unroll
        for (int kk = 0; kk < 64; kk += 4) {
            float a0 = As[kk + 0][lane];
            float a1 = As[kk + 1][lane];
            float a2 = As[kk + 2][lane];
            float a3 = As[kk + 3][lane];
#pragma unroll
            for (int j = 0; j < 8; j++) {
                float4 sv = *(const float4*)&Ss[b0 + j][kk];
                acc[j] = fmaf(a0, sv.x, acc[j]);
                acc[j] = fmaf(a1, sv.y, acc[j]);
                acc[j] = fmaf(a2, sv.z, acc[j]);
                acc[j] = fmaf(a3, sv.w, acc[j]);
            }
        }
        __syncthreads();
    }

    // epilogue
    const int h = h0 + lane;
    const float* __restrict__ U = &g_U[layer][0][0];
#pragma unroll
    for (int j = 0; j < 8; j++) {
        int b = b0 + j;
        size_t row_t  = ((size_t)(layer * BATCH + b) * (FRAMES + 1) + t) * N_HID + h;
        size_t row_t1 = row_t + N_HID;
        float u = U[((size_t)b * FRAMES + t) * N_HID + h];
        float sprev = spikes[row_t];
        float mprev = mems[row_t];
        float y = tanhf(ALPHA * acc[j] + (1.0f - ALPHA) * u);
        float mn = DECAY * mprev - THR * (1.0f - sprev) + y;
        float sn = (mn > THR) ? 1.0f : 0.0f;
        mems[row_t1] = mn;
        spikes[row_t1] = sn;
    }
}

// ---------------------------------------------------------------------------
// Launch
// Inputs (metadata order): x, W_in1, A1, b1, W_in2, A2, b2, mem0_1, mem0_2
// ---------------------------------------------------------------------------
extern "C" void kernel_launch(void* const* d_in, const int* in_sizes, int n_in,
                              void* d_out, int out_size)
{
    const float* x     = (const float*)d_in[0];
    const float* W_in1 = (const float*)d_in[1];
    const float* A1    = (const float*)d_in[2];
    const float* b1    = (const float*)d_in[3];
    const float* W_in2 = (const float*)d_in[4];
    const float* A2    = (const float*)d_in[5];
    const float* b2    = (const float*)d_in[6];
    const float* mem0_1 = (const float*)d_in[7];
    const float* mem0_2 = (const float*)d_in[8];
    float* out = (float*)d_out;

    // Feedforward drive for all frames (both layers)
    {
        dim3 grid(N_HID / 128, (BATCH * FRAMES) / 128, 2);
        ff_kernel<<<grid, 256>>>(x, W_in1, b1, W_in2, b2);
    }
    // t=0 state into output buffer
    {
        int total = 2 * BATCH * N_HID;
        init_kernel<<<(total + 255) / 256, 256>>>(mem0_1, mem0_2, out);
    }
    // Sequential time loop
    for (int t = 0; t < FRAMES; t++) {
        step_kernel<<<128, 256>>>(A1, A2, out, t);
    }
}

// round 3
// speedup vs baseline: 1.0587x; 1.0587x over previous
#include <cuda_runtime.h>
#include <cuda_bf16.h>
#include <mma.h>
#include <math.h>

using namespace nvcuda;

#define BATCH 64
#define FRAMES 128
#define N_IN 512
#define N_HID 2048
#define ALPHA 0.5f
#define DECAY 0.5f
#define THR 0.5f

#define MEMS_ELEMS ((size_t)2 * BATCH * (FRAMES + 1) * N_HID)

// ---------------------------------------------------------------------------
// Device scratch
// ---------------------------------------------------------------------------
__device__ float g_U[2][BATCH * FRAMES][N_HID];  // x@W + bias
// A limbs, packed per 32-column tile for contiguous per-CTA streaming:
// [layer][ntile][k][limb][col32]
__device__ __nv_bfloat16 g_Apack[2][64][N_HID][4][32];

// ---------------------------------------------------------------------------
// 4-limb bf16 split (RN chain): a = l0+l1+l2+l3 + r, |r| <= 2^-32 |a|
// ---------------------------------------------------------------------------
__global__ void prep_A4_kernel(const float* __restrict__ A1,
                               const float* __restrict__ A2)
{
    size_t per = (size_t)N_HID * N_HID;
    size_t idx = (size_t)blockIdx.x * blockDim.x + threadIdx.x;
    if (idx >= 2 * per) return;
    int layer = (int)(idx / per);
    size_t rem = idx % per;
    int k = (int)(rem / N_HID);
    int n = (int)(rem % N_HID);
    float a = (layer ? A2 : A1)[rem];

    __nv_bfloat16 L[4];
    float r = a;
#pragma unroll
    for (int i = 0; i < 4; i++) {
        L[i] = __float2bfloat16(r);
        r -= __bfloat162float(L[i]);
    }
    int nt = n >> 5, col = n & 31;
#pragma unroll
    for (int i = 0; i < 4; i++)
        g_Apack[layer][nt][k][i][col] = L[i];
}

// ---------------------------------------------------------------------------
// Feedforward GEMM (proven fp32 SIMT from R1): U[l] = x @ W_l + b_l
// ---------------------------------------------------------------------------
__global__ void __launch_bounds__(256) ff_kernel(
    const float* __restrict__ x,
    const float* __restrict__ W1, const float* __restrict__ b1,
    const float* __restrict__ W2, const float* __restrict__ b2)
{
    const int layer = blockIdx.z;
    const float* __restrict__ W = layer ? W2 : W1;
    const float* __restrict__ bias = layer ? b2 : b1;
    const int m0 = blockIdx.y * 128;
    const int n0 = blockIdx.x * 128;

    __shared__ float xs[16][128];
    __shared__ float ws[16][128];

    const int tid = threadIdx.x;
    const int tx = tid & 15;
    const int ty = tid >> 4;

    float acc[8][8];
#pragma unroll
    for (int i = 0; i < 8; i++)
#pragma unroll
        for (int j = 0; j < 8; j++) acc[i][j] = 0.f;

    for (int k0 = 0; k0 < N_IN; k0 += 16) {
#pragma unroll
        for (int i = 0; i < 2; i++) {
            int idx = tid + i * 256;
            int row = idx >> 2;
            int c4 = idx & 3;
            float4 v = *(const float4*)&x[(size_t)(m0 + row) * N_IN + k0 + c4 * 4];
            xs[c4 * 4 + 0][row] = v.x;
            xs[c4 * 4 + 1][row] = v.y;
            xs[c4 * 4 + 2][row] = v.z;
            xs[c4 * 4 + 3][row] = v.w;
        }
#pragma unroll
        for (int i = 0; i < 2; i++) {
            int idx = tid + i * 256;
            int row = idx >> 5;
            int c4 = idx & 31;
            float4 v = *(const float4*)&W[(size_t)(k0 + row) * N_HID + n0 + c4 * 4];
            *(float4*)&ws[row][c4 * 4] = v;
        }
        __syncthreads();

#pragma unroll
        for (int k = 0; k < 16; k++) {
            float a[8], bb[8];
            *(float4*)&a[0] = *(const float4*)&xs[k][ty * 4];
            *(float4*)&a[4] = *(const float4*)&xs[k][ty * 4 + 64];
            *(float4*)&bb[0] = *(const float4*)&ws[k][tx * 4];
            *(float4*)&bb[4] = *(const float4*)&ws[k][tx * 4 + 64];
#pragma unroll
            for (int i = 0; i < 8; i++)
#pragma unroll
                for (int j = 0; j < 8; j++)
                    acc[i][j] = fmaf(a[i], bb[j], acc[i][j]);
        }
        __syncthreads();
    }

    float* __restrict__ U = &g_U[layer][0][0];
#pragma unroll
    for (int i = 0; i < 8; i++) {
        int m = m0 + ty * 4 + (i & 3) + (i >> 2) * 64;
#pragma unroll
        for (int j = 0; j < 8; j++) {
            int n = n0 + tx * 4 + (j & 3) + (j >> 2) * 64;
            U[(size_t)m * N_HID + n] = acc[i][j] + bias[n];
        }
    }
}

// ---------------------------------------------------------------------------
// Init t=0 state
// ---------------------------------------------------------------------------
__global__ void init_kernel(const float* __restrict__ mem0_1,
                            const float* __restrict__ mem0_2,
                            float* __restrict__ out)
{
    float* mems = out;
    float* spikes = out + MEMS_ELEMS;
    size_t idx = (size_t)blockIdx.x * blockDim.x + threadIdx.x;
    size_t total = (size_t)2 * BATCH * N_HID;
    if (idx >= total) return;
    int l = (int)(idx / ((size_t)BATCH * N_HID));
    size_t rem = idx % ((size_t)BATCH * N_HID);
    int b = (int)(rem / N_HID);
    int h = (int)(rem % N_HID);
    const float* m0 = l ? mem0_2 : mem0_1;
    size_t o = ((size_t)(l * BATCH + b) * (FRAMES + 1)) * N_HID + h;
    mems[o] = m0[(size_t)b * N_HID + h];
    spikes[o] = 0.f;
}

// ---------------------------------------------------------------------------
// Fused step: Y = s_t @ A via wmma bf16 with 4 exact-ish limbs (spikes are
// exact in bf16), 4 independent accumulator chains, fused LIF epilogue.
// Grid: 128 CTAs = 2 layers x 64 col-tiles of 32. Block 256 (8 warps).
// ---------------------------------------------------------------------------
#define KC 64

__global__ void __launch_bounds__(256) step_mma_kernel(float* __restrict__ out, int t)
{
    const int bx = blockIdx.x;
    const int layer = bx >> 6;
    const int nt = bx & 63;
    const int n0 = nt * 32;

    __shared__ __nv_bfloat16 Ss[64][KC + 8];     // spikes [b][k], stride 72
    __shared__ __nv_bfloat16 Bs[4][KC][40];      // A limbs [limb][k][n]
    __shared__ float Cs[64][36];                 // result staging

    const int tid = threadIdx.x;
    const int wid = tid >> 5;
    const int wm = wid >> 1;   // 0..3 m-tile
    const int wn = wid & 1;    // 0..1 n-tile

    float* mems = out;
    float* spikes = out + MEMS_ELEMS;

    const __nv_bfloat16* __restrict__ Abase = &g_Apack[layer][nt][0][0][0];
    const float* __restrict__ sbase =
        spikes + ((size_t)(layer * BATCH) * (FRAMES + 1) + t) * N_HID;

    wmma::fragment<wmma::accumulator, 16, 16, 16, float> c[4];
#pragma unroll
    for (int i = 0; i < 4; i++) wmma::fill_fragment(c[i], 0.0f);

    // staging maps (constant per thread)
    const int sb = tid >> 2;          // 0..63  spike row
    const int sq = (tid & 3) * 16;    // col group of 16
    const int ak = tid >> 2;          // 0..63  A k-row
    const int al = tid & 3;           // limb

#pragma unroll 1
    for (int k0 = 0; k0 < N_HID; k0 += KC) {
        // stage spikes: 64 x 64 fp32 -> bf16
        {
            const float* srow = sbase + (size_t)sb * (FRAMES + 1) * N_HID + k0 + sq;
#pragma unroll
            for (int i = 0; i < 4; i++) {
                float4 v = *(const float4*)&srow[i * 4];
                __nv_bfloat162 p0 = __floats2bfloat162_rn(v.x, v.y);
                __nv_bfloat162 p1 = __floats2bfloat162_rn(v.z, v.w);
                *(__nv_bfloat162*)&Ss[sb][sq + i * 4] = p0;
                *(__nv_bfloat162*)&Ss[sb][sq + i * 4 + 2] = p1;
            }
        }
        // stage A limbs: contiguous 16KB stream; thread copies one 64B row
        {
            const uint4* src = (const uint4*)(Abase + ((size_t)(k0 + ak) * 4 + al) * 32);
            uint4* dst = (uint4*)&Bs[al][ak][0];
            dst[0] = src[0];
            dst[1] = src[1];
            dst[2] = src[2];
            dst[3] = src[3];
        }
        __syncthreads();

#pragma unroll
        for (int ks = 0; ks < KC / 16; ks++) {
            wmma::fragment<wmma::matrix_a, 16, 16, 16, __nv_bfloat16, wmma::row_major> af;
            wmma::load_matrix_sync(af, &Ss[wm * 16][ks * 16], KC + 8);
#pragma unroll
            for (int l = 0; l < 4; l++) {
                wmma::fragment<wmma::matrix_b, 16, 16, 16, __nv_bfloat16, wmma::row_major> bfr;
                wmma::load_matrix_sync(bfr, &Bs[l][ks * 16][wn * 16], 40);
                wmma::mma_sync(c[l], af, bfr, c[l]);
            }
        }
        __syncthreads();
    }

    // sum the 4 limb accumulators elementwise (identical layouts)
#pragma unroll
    for (int e = 0; e < c[0].num_elements; e++)
        c[0].x[e] = (c[0].x[e] + c[1].x[e]) + (c[2].x[e] + c[3].x[e]);

    wmma::store_matrix_sync(&Cs[wm * 16][wn * 16], c[0], 36, wmma::mem_row_major);
    __syncthreads();

    // fused LIF epilogue (U already contains bias)
#pragma unroll
    for (int e = 0; e < 8; e++) {
        int flat = tid + e * 256;   // 0..2047
        int b = flat >> 5;
        int hl = flat & 31;
        int h = n0 + hl;
        float p = Cs[b][hl];
        float u = g_U[layer][b * FRAMES + t][h];
        size_t row_t = ((size_t)(layer * BATCH + b) * (FRAMES + 1) + t) * N_HID + h;
        float mprev = mems[row_t];
        float sprev = spikes[row_t];
        float y = tanhf(ALPHA * p + (1.0f - ALPHA) * u);
        float mn = DECAY * mprev - THR * (1.0f - sprev) + y;
        mems[row_t + N_HID] = mn;
        spikes[row_t + N_HID] = (mn > THR) ? 1.0f : 0.0f;
    }
}

// ---------------------------------------------------------------------------
// Launch. Inputs: x, W_in1, A1, b1, W_in2, A2, b2, mem0_1, mem0_2
// ---------------------------------------------------------------------------
extern "C" void kernel_launch(void* const* d_in, const int* in_sizes, int n_in,
                              void* d_out, int out_size)
{
    const float* x      = (const float*)d_in[0];
    const float* W_in1  = (const float*)d_in[1];
    const float* A1     = (const float*)d_in[2];
    const float* b1     = (const float*)d_in[3];
    const float* W_in2  = (const float*)d_in[4];
    const float* A2     = (const float*)d_in[5];
    const float* b2     = (const float*)d_in[6];
    const float* mem0_1 = (const float*)d_in[7];
    const float* mem0_2 = (const float*)d_in[8];
    float* out = (float*)d_out;

    // A limb pack (runs every call; inputs may change)
    {
        size_t n = (size_t)2 * N_HID * N_HID;
        prep_A4_kernel<<<(unsigned)((n + 255) / 256), 256>>>(A1, A2);
    }
    // Feedforward drive (fp32 SIMT, includes bias)
    {
        dim3 grid(N_HID / 128, (BATCH * FRAMES) / 128, 2);
        ff_kernel<<<grid, 256>>>(x, W_in1, b1, W_in2, b2);
    }
    // t=0 state
    {
        int total = 2 * BATCH * N_HID;
        init_kernel<<<(total + 255) / 256, 256>>>(mem0_1, mem0_2, out);
    }
    // Sequential time loop
    for (int t = 0; t < FRAMES; t++) {
        step_mma_kernel<<<128, 256>>>(out, t);
    }
}

// round 6
// speedup vs baseline: 1.4542x; 1.3735x over previous
#include <cuda_runtime.h>
#include <cuda_bf16.h>
#include <mma.h>
#include <math.h>
#include <cstdint>
#include <cstddef>

using namespace nvcuda;

#define BATCH 64
#define FRAMES 128
#define N_IN 512
#define N_HID 2048
#define ALPHA 0.5f
#define DECAY 0.5f
#define THR 0.5f

#define MEMS_ELEMS ((size_t)2 * BATCH * (FRAMES + 1) * N_HID)

// ---------------------------------------------------------------------------
// Device scratch
// ---------------------------------------------------------------------------
__device__ float g_U[2][BATCH * FRAMES][N_HID];  // x@W + bias (streamed, evict-first)
// A limbs, packed fully contiguous per (layer, ntile):
// [layer][ntile(64)][chunk(16)][limb(4)][kin(128)][col(32)]  bf16  (64MB)
__device__ __nv_bfloat16 g_Apack[(size_t)2 * 64 * 16 * 4 * 128 * 32];
// bf16 spike scratch, ping-pong by step parity: [par][layer][b][h]  (1MB)
__device__ __nv_bfloat16 g_sbf[2][2][BATCH][N_HID];

// ---------------------------------------------------------------------------
// 4-limb bf16 split + pack
// ---------------------------------------------------------------------------
__global__ void prep_A4_kernel(const float* __restrict__ A1,
                               const float* __restrict__ A2)
{
    size_t per = (size_t)N_HID * N_HID;
    size_t idx = (size_t)blockIdx.x * blockDim.x + threadIdx.x;
    if (idx >= 2 * per) return;
    int layer = (int)(idx / per);
    size_t rem = idx % per;
    int k = (int)(rem / N_HID);
    int n = (int)(rem % N_HID);
    float a = (layer ? A2 : A1)[rem];

    int nt = n >> 5, col = n & 31;
    int chunk = k >> 7, kin = k & 127;
    size_t base = ((((size_t)(layer * 64 + nt) * 16 + chunk) * 4) * 128 + kin) * 32 + col;

    float r = a;
#pragma unroll
    for (int i = 0; i < 4; i++) {
        __nv_bfloat16 L = __float2bfloat16(r);
        r -= __bfloat162float(L);
        g_Apack[base + (size_t)i * (128 * 32)] = L;
    }
}

// ---------------------------------------------------------------------------
// Feedforward GEMM (proven fp32 SIMT): U[l] = x @ W_l + b_l
// ---------------------------------------------------------------------------
__global__ void __launch_bounds__(256) ff_kernel(
    const float* __restrict__ x,
    const float* __restrict__ W1, const float* __restrict__ b1,
    const float* __restrict__ W2, const float* __restrict__ b2)
{
    const int layer = blockIdx.z;
    const float* __restrict__ W = layer ? W2 : W1;
    const float* __restrict__ bias = layer ? b2 : b1;
    const int m0 = blockIdx.y * 128;
    const int n0 = blockIdx.x * 128;

    __shared__ float xs[16][128];
    __shared__ float ws[16][128];

    const int tid = threadIdx.x;
    const int tx = tid & 15;
    const int ty = tid >> 4;

    float acc[8][8];
#pragma unroll
    for (int i = 0; i < 8; i++)
#pragma unroll
        for (int j = 0; j < 8; j++) acc[i][j] = 0.f;

    for (int k0 = 0; k0 < N_IN; k0 += 16) {
#pragma unroll
        for (int i = 0; i < 2; i++) {
            int idx = tid + i * 256;
            int row = idx >> 2;
            int c4 = idx & 3;
            float4 v = *(const float4*)&x[(size_t)(m0 + row) * N_IN + k0 + c4 * 4];
            xs[c4 * 4 + 0][row] = v.x;
            xs[c4 * 4 + 1][row] = v.y;
            xs[c4 * 4 + 2][row] = v.z;
            xs[c4 * 4 + 3][row] = v.w;
        }
#pragma unroll
        for (int i = 0; i < 2; i++) {
            int idx = tid + i * 256;
            int row = idx >> 5;
            int c4 = idx & 31;
            float4 v = *(const float4*)&W[(size_t)(k0 + row) * N_HID + n0 + c4 * 4];
            *(float4*)&ws[row][c4 * 4] = v;
        }
        __syncthreads();

#pragma unroll
        for (int k = 0; k < 16; k++) {
            float a[8], bb[8];
            *(float4*)&a[0] = *(const float4*)&xs[k][ty * 4];
            *(float4*)&a[4] = *(const float4*)&xs[k][ty * 4 + 64];
            *(float4*)&bb[0] = *(const float4*)&ws[k][tx * 4];
            *(float4*)&bb[4] = *(const float4*)&ws[k][tx * 4 + 64];
#pragma unroll
            for (int i = 0; i < 8; i++)
#pragma unroll
                for (int j = 0; j < 8; j++)
                    acc[i][j] = fmaf(a[i], bb[j], acc[i][j]);
        }
        __syncthreads();
    }

    float* __restrict__ U = &g_U[layer][0][0];
#pragma unroll
    for (int i = 0; i < 8; i++) {
        int m = m0 + ty * 4 + (i & 3) + (i >> 2) * 64;
#pragma unroll
        for (int j = 0; j < 8; j++) {
            int n = n0 + tx * 4 + (j & 3) + (j >> 2) * 64;
            U[(size_t)m * N_HID + n] = acc[i][j] + bias[n];
        }
    }
}

// ---------------------------------------------------------------------------
// Init t=0 state (fp32 outputs + bf16 scratch parity 0)
// ---------------------------------------------------------------------------
__global__ void init_kernel(const float* __restrict__ mem0_1,
                            const float* __restrict__ mem0_2,
                            float* __restrict__ out)
{
    float* mems = out;
    float* spikes = out + MEMS_ELEMS;
    size_t idx = (size_t)blockIdx.x * blockDim.x + threadIdx.x;
    size_t total = (size_t)2 * BATCH * N_HID;
    if (idx >= total) return;
    int l = (int)(idx / ((size_t)BATCH * N_HID));
    size_t rem = idx % ((size_t)BATCH * N_HID);
    int b = (int)(rem / N_HID);
    int h = (int)(rem % N_HID);
    const float* m0 = l ? mem0_2 : mem0_1;
    size_t o = ((size_t)(l * BATCH + b) * (FRAMES + 1)) * N_HID + h;
    mems[o] = m0[(size_t)b * N_HID + h];
    spikes[o] = 0.f;
    g_sbf[0][l][b][h] = __float2bfloat16(0.f);
}

// ---------------------------------------------------------------------------
// Fused pipelined step. Grid 128 = 2 layers x 64 coltiles(32). Block 256.
// KC=128 K-chunk, 3-stage cp.async pipeline; 4 limb accumulator chains.
// ---------------------------------------------------------------------------
#define KC 128
#define NCH (N_HID / KC)                   // 16 chunks
#define SS_STAGE_BYTES (64 * 272)          // 64 rows x 136 bf16
#define AS_STAGE_BYTES (512 * 80)          // 4 limbs x 128 k x 40 bf16
#define SS_OFF 0
#define AS_OFF (3 * SS_STAGE_BYTES)                 // 52224
#define CS_OFF (AS_OFF + 3 * AS_STAGE_BYTES)        // 175104
#define STEP_SMEM_BYTES (CS_OFF + 64 * 36 * 4)      // 184320

__device__ __forceinline__ void cpasync16(unsigned int dst, const void* src)
{
    asm volatile("cp.async.cg.shared.global [%0], [%1], 16;\n" ::"r"(dst), "l"(src));
}

extern __shared__ char smem_buf[];

__global__ void __launch_bounds__(256) step_mma_kernel(float* __restrict__ out, int t)
{
    const int bx = blockIdx.x;
    const int layer = bx >> 6;
    const int nt = bx & 63;
    const int n0 = nt * 32;

    const int tid = threadIdx.x;
    const int wid = tid >> 5;
    const int wm = wid >> 1;   // 0..3
    const int wn = wid & 1;    // 0..1

    float* mems = out;
    float* spikes = out + MEMS_ELEMS;

    const __nv_bfloat16* __restrict__ Abase =
        g_Apack + (size_t)(layer * 64 + nt) * (16 * 4 * 128 * 32);
    const __nv_bfloat16* __restrict__ gS = &g_sbf[t & 1][layer][0][0];

    const unsigned int smem_u32 = (unsigned int)__cvta_generic_to_shared(smem_buf);

    wmma::fragment<wmma::accumulator, 16, 16, 16, float> acc[4];
#pragma unroll
    for (int i = 0; i < 4; i++) wmma::fill_fragment(acc[i], 0.0f);

    // per-thread copy maps
    const int aj = tid & 3;          // 16B chunk within 64B A row
    const int ar0 = tid >> 2;        // A row group (0..63)
    const int sb = tid >> 2;         // spike row (0..63)
    const int scb = tid & 3;         // spike 16B chunk base

    // stage-issue helper (lambda avoids macro/_Pragma breakage)
    auto issue_stage = [&](int c, int s) {
        const char* srcA = (const char*)(Abase + (size_t)c * 16384);
        unsigned int dstA = smem_u32 + AS_OFF + s * AS_STAGE_BYTES;
#pragma unroll
        for (int i = 0; i < 8; i++) {
            int r = ar0 + i * 64;    // 0..511 (A k-limb row of 64B)
            cpasync16(dstA + r * 80 + aj * 16, srcA + r * 64 + aj * 16);
        }
        const char* srcS = (const char*)(gS + (size_t)sb * N_HID + c * KC);
        unsigned int dstS = smem_u32 + SS_OFF + s * SS_STAGE_BYTES + sb * 272;
#pragma unroll
        for (int i = 0; i < 4; i++) {
            int cc = scb + i * 4;    // 16 x 16B = 256B row
            cpasync16(dstS + cc * 16, srcS + cc * 16);
        }
        asm volatile("cp.async.commit_group;\n" ::: "memory");
    };

    issue_stage(0, 0);
    issue_stage(1, 1);

#pragma unroll 1
    for (int c = 0; c < NCH; c++) {
        if (c + 1 < NCH)
            asm volatile("cp.async.wait_group 1;\n" ::: "memory");
        else
            asm volatile("cp.async.wait_group 0;\n" ::: "memory");
        __syncthreads();

        if (c + 2 < NCH) issue_stage(c + 2, (c + 2) % 3);

        const int s = c % 3;
        const __nv_bfloat16* ssb =
            (const __nv_bfloat16*)(smem_buf + SS_OFF + s * SS_STAGE_BYTES);
        const __nv_bfloat16* asb =
            (const __nv_bfloat16*)(smem_buf + AS_OFF + s * AS_STAGE_BYTES);

#pragma unroll
        for (int ks = 0; ks < KC / 16; ks++) {
            wmma::fragment<wmma::matrix_a, 16, 16, 16, __nv_bfloat16, wmma::row_major> af;
            wmma::load_matrix_sync(af, ssb + (wm * 16) * 136 + ks * 16, 136);
#pragma unroll
            for (int l = 0; l < 4; l++) {
                wmma::fragment<wmma::matrix_b, 16, 16, 16, __nv_bfloat16, wmma::row_major> bfr;
                wmma::load_matrix_sync(bfr, asb + (l * 128 + ks * 16) * 40 + wn * 16, 40);
                wmma::mma_sync(acc[l], af, bfr, acc[l]);
            }
        }
    }

    // combine limb accumulators and stage result
#pragma unroll
    for (int e = 0; e < acc[0].num_elements; e++)
        acc[0].x[e] = (acc[0].x[e] + acc[1].x[e]) + (acc[2].x[e] + acc[3].x[e]);

    float* Cs = (float*)(smem_buf + CS_OFF);
    __syncthreads();
    wmma::store_matrix_sync(Cs + (wm * 16) * 36 + wn * 16, acc[0], 36, wmma::mem_row_major);
    __syncthreads();

    // fused LIF epilogue
    __nv_bfloat16* gSn = &g_sbf[(t + 1) & 1][layer][0][0];
#pragma unroll
    for (int e = 0; e < 8; e++) {
        int flat = tid + e * 256;   // 0..2047
        int b = flat >> 5;
        int hl = flat & 31;
        int h = n0 + hl;
        float p = Cs[b * 36 + hl];
        float u = __ldcs(&g_U[layer][b * FRAMES + t][h]);
        size_t row_t = ((size_t)(layer * BATCH + b) * (FRAMES + 1) + t) * N_HID + h;
        float mprev = mems[row_t];
        float sprev = __bfloat162float(gS[(size_t)b * N_HID + h]);
        float y = tanhf(ALPHA * p + (1.0f - ALPHA) * u);
        float mn = DECAY * mprev - THR * (1.0f - sprev) + y;
        float sn = (mn > THR) ? 1.0f : 0.0f;
        mems[row_t + N_HID] = mn;
        __stcs(&spikes[row_t + N_HID], sn);
        gSn[(size_t)b * N_HID + h] = __float2bfloat16(sn);
    }
}

// ---------------------------------------------------------------------------
// Launch. Inputs: x, W_in1, A1, b1, W_in2, A2, b2, mem0_1, mem0_2
// ---------------------------------------------------------------------------
extern "C" void kernel_launch(void* const* d_in, const int* in_sizes, int n_in,
                              void* d_out, int out_size)
{
    const float* x      = (const float*)d_in[0];
    const float* W_in1  = (const float*)d_in[1];
    const float* A1     = (const float*)d_in[2];
    const float* b1     = (const float*)d_in[3];
    const float* W_in2  = (const float*)d_in[4];
    const float* A2     = (const float*)d_in[5];
    const float* b2     = (const float*)d_in[6];
    const float* mem0_1 = (const float*)d_in[7];
    const float* mem0_2 = (const float*)d_in[8];
    float* out = (float*)d_out;

    cudaFuncSetAttribute(step_mma_kernel,
                         cudaFuncAttributeMaxDynamicSharedMemorySize,
                         STEP_SMEM_BYTES);

    // A limb pack
    {
        size_t n = (size_t)2 * N_HID * N_HID;
        prep_A4_kernel<<<(unsigned)((n + 255) / 256), 256>>>(A1, A2);
    }
    // Feedforward drive (includes bias)
    {
        dim3 grid(N_HID / 128, (BATCH * FRAMES) / 128, 2);
        ff_kernel<<<grid, 256>>>(x, W_in1, b1, W_in2, b2);
    }
    // t=0 state
    {
        int total = 2 * BATCH * N_HID;
        init_kernel<<<(total + 255) / 256, 256>>>(mem0_1, mem0_2, out);
    }
    // Sequential time loop
    for (int t = 0; t < FRAMES; t++) {
        step_mma_kernel<<<128, 256, STEP_SMEM_BYTES>>>(out, t);
    }
}

// round 7
// speedup vs baseline: 1.4709x; 1.0115x over previous
#include <cuda_runtime.h>
#include <cuda_bf16.h>
#include <mma.h>
#include <math.h>
#include <cstdint>
#include <cstddef>

using namespace nvcuda;

#define BATCH 64
#define FRAMES 128
#define N_IN 512
#define N_HID 2048
#define ALPHA 0.5f
#define DECAY 0.5f
#define THR 0.5f

#define MEMS_ELEMS ((size_t)2 * BATCH * (FRAMES + 1) * N_HID)

// ---------------------------------------------------------------------------
// Device scratch
// ---------------------------------------------------------------------------
__device__ float g_U[2][BATCH * FRAMES][N_HID];  // x@W + bias (streamed, evict-first)
// A limbs, packed fully contiguous per (layer, ntile):
// [layer][ntile(64)][chunk(16)][limb(4)][kin(128)][col(32)]  bf16  (64MB)
__device__ __nv_bfloat16 g_Apack[(size_t)2 * 64 * 16 * 4 * 128 * 32];
// bf16 spike scratch, ping-pong by step parity: [par][layer][b][h]  (1MB)
__device__ __nv_bfloat16 g_sbf[2][2][BATCH][N_HID];

// ---------------------------------------------------------------------------
// 4-limb bf16 split + pack
// ---------------------------------------------------------------------------
__global__ void prep_A4_kernel(const float* __restrict__ A1,
                               const float* __restrict__ A2)
{
    size_t per = (size_t)N_HID * N_HID;
    size_t idx = (size_t)blockIdx.x * blockDim.x + threadIdx.x;
    if (idx >= 2 * per) return;
    int layer = (int)(idx / per);
    size_t rem = idx % per;
    int k = (int)(rem / N_HID);
    int n = (int)(rem % N_HID);
    float a = (layer ? A2 : A1)[rem];

    int nt = n >> 5, col = n & 31;
    int chunk = k >> 7, kin = k & 127;
    size_t base = ((((size_t)(layer * 64 + nt) * 16 + chunk) * 4) * 128 + kin) * 32 + col;

    float r = a;
#pragma unroll
    for (int i = 0; i < 4; i++) {
        __nv_bfloat16 L = __float2bfloat16(r);
        r -= __bfloat162float(L);
        g_Apack[base + (size_t)i * (128 * 32)] = L;
    }
}

// ---------------------------------------------------------------------------
// Feedforward GEMM (proven fp32 SIMT): U[l] = x @ W_l + b_l
// ---------------------------------------------------------------------------
__global__ void __launch_bounds__(256) ff_kernel(
    const float* __restrict__ x,
    const float* __restrict__ W1, const float* __restrict__ b1,
    const float* __restrict__ W2, const float* __restrict__ b2)
{
    const int layer = blockIdx.z;
    const float* __restrict__ W = layer ? W2 : W1;
    const float* __restrict__ bias = layer ? b2 : b1;
    const int m0 = blockIdx.y * 128;
    const int n0 = blockIdx.x * 128;

    __shared__ float xs[16][128];
    __shared__ float ws[16][128];

    const int tid = threadIdx.x;
    const int tx = tid & 15;
    const int ty = tid >> 4;

    float acc[8][8];
#pragma unroll
    for (int i = 0; i < 8; i++)
#pragma unroll
        for (int j = 0; j < 8; j++) acc[i][j] = 0.f;

    for (int k0 = 0; k0 < N_IN; k0 += 16) {
#pragma unroll
        for (int i = 0; i < 2; i++) {
            int idx = tid + i * 256;
            int row = idx >> 2;
            int c4 = idx & 3;
            float4 v = *(const float4*)&x[(size_t)(m0 + row) * N_IN + k0 + c4 * 4];
            xs[c4 * 4 + 0][row] = v.x;
            xs[c4 * 4 + 1][row] = v.y;
            xs[c4 * 4 + 2][row] = v.z;
            xs[c4 * 4 + 3][row] = v.w;
        }
#pragma unroll
        for (int i = 0; i < 2; i++) {
            int idx = tid + i * 256;
            int row = idx >> 5;
            int c4 = idx & 31;
            float4 v = *(const float4*)&W[(size_t)(k0 + row) * N_HID + n0 + c4 * 4];
            *(float4*)&ws[row][c4 * 4] = v;
        }
        __syncthreads();

#pragma unroll
        for (int k = 0; k < 16; k++) {
            float a[8], bb[8];
            *(float4*)&a[0] = *(const float4*)&xs[k][ty * 4];
            *(float4*)&a[4] = *(const float4*)&xs[k][ty * 4 + 64];
            *(float4*)&bb[0] = *(const float4*)&ws[k][tx * 4];
            *(float4*)&bb[4] = *(const float4*)&ws[k][tx * 4 + 64];
#pragma unroll
            for (int i = 0; i < 8; i++)
#pragma unroll
                for (int j = 0; j < 8; j++)
                    acc[i][j] = fmaf(a[i], bb[j], acc[i][j]);
        }
        __syncthreads();
    }

    float* __restrict__ U = &g_U[layer][0][0];
#pragma unroll
    for (int i = 0; i < 8; i++) {
        int m = m0 + ty * 4 + (i & 3) + (i >> 2) * 64;
#pragma unroll
        for (int j = 0; j < 8; j++) {
            int n = n0 + tx * 4 + (j & 3) + (j >> 2) * 64;
            U[(size_t)m * N_HID + n] = acc[i][j] + bias[n];
        }
    }
}

// ---------------------------------------------------------------------------
// Init t=0 state (fp32 outputs + bf16 scratch parity 0)
// ---------------------------------------------------------------------------
__global__ void init_kernel(const float* __restrict__ mem0_1,
                            const float* __restrict__ mem0_2,
                            float* __restrict__ out)
{
    float* mems = out;
    float* spikes = out + MEMS_ELEMS;
    size_t idx = (size_t)blockIdx.x * blockDim.x + threadIdx.x;
    size_t total = (size_t)2 * BATCH * N_HID;
    if (idx >= total) return;
    int l = (int)(idx / ((size_t)BATCH * N_HID));
    size_t rem = idx % ((size_t)BATCH * N_HID);
    int b = (int)(rem / N_HID);
    int h = (int)(rem % N_HID);
    const float* m0 = l ? mem0_2 : mem0_1;
    size_t o = ((size_t)(l * BATCH + b) * (FRAMES + 1)) * N_HID + h;
    mems[o] = m0[(size_t)b * N_HID + h];
    spikes[o] = 0.f;
    g_sbf[0][l][b][h] = __float2bfloat16(0.f);
}

// ---------------------------------------------------------------------------
// Fused pipelined step. Grid 128 = 2 layers x 64 coltiles(32). Block 512.
// 16 warps: group g = limb pair {2g, 2g+1}; within group 4m x 2n tile map.
// KC=128 K-chunk, 3-stage cp.async pipeline.
// ---------------------------------------------------------------------------
#define KC 128
#define NCH (N_HID / KC)                   // 16 chunks
#define SS_STAGE_BYTES (64 * 272)          // 64 rows x 136 bf16
#define AS_STAGE_BYTES (512 * 80)          // 4 limbs x 128 k x 40 bf16
#define SS_OFF 0
#define AS_OFF (3 * SS_STAGE_BYTES)                 // 52224
#define CSA_OFF (AS_OFF + 3 * AS_STAGE_BYTES)       // 175104
#define CSB_OFF (CSA_OFF + 64 * 36 * 4)             // 184320
#define STEP_SMEM_BYTES (CSB_OFF + 64 * 36 * 4)     // 193536

__device__ __forceinline__ void cpasync16(unsigned int dst, const void* src)
{
    asm volatile("cp.async.cg.shared.global [%0], [%1], 16;\n" ::"r"(dst), "l"(src));
}

extern __shared__ char smem_buf[];

__global__ void __launch_bounds__(512) step_mma_kernel(float* __restrict__ out, int t)
{
    const int bx = blockIdx.x;
    const int layer = bx >> 6;
    const int nt = bx & 63;
    const int n0 = nt * 32;

    const int tid = threadIdx.x;
    const int wid = tid >> 5;
    const int g  = wid >> 3;       // limb-pair group: 0 -> {0,1}, 1 -> {2,3}
    const int w8 = wid & 7;
    const int wm = w8 >> 1;        // 0..3 m-tile
    const int wn = w8 & 1;         // 0..1 n-tile

    float* mems = out;
    float* spikes = out + MEMS_ELEMS;

    const __nv_bfloat16* __restrict__ Abase =
        g_Apack + (size_t)(layer * 64 + nt) * (16 * 4 * 128 * 32);
    const __nv_bfloat16* __restrict__ gS = &g_sbf[t & 1][layer][0][0];

    const unsigned int smem_u32 = (unsigned int)__cvta_generic_to_shared(smem_buf);

    wmma::fragment<wmma::accumulator, 16, 16, 16, float> acc[2];
#pragma unroll
    for (int i = 0; i < 2; i++) wmma::fill_fragment(acc[i], 0.0f);

    // per-thread copy maps (512 threads)
    const int aj = tid & 3;          // 16B chunk within 64B A row
    const int ar0 = tid >> 2;        // A row group (0..127)
    const int sb = tid >> 3;         // spike row (0..63)
    const int scb = tid & 7;         // spike 16B chunk base

    auto issue_stage = [&](int c, int s) {
        const char* srcA = (const char*)(Abase + (size_t)c * 16384);
        unsigned int dstA = smem_u32 + AS_OFF + s * AS_STAGE_BYTES;
#pragma unroll
        for (int i = 0; i < 4; i++) {
            int r = ar0 + i * 128;   // 0..511 (A k-limb row of 64B)
            cpasync16(dstA + r * 80 + aj * 16, srcA + r * 64 + aj * 16);
        }
        const char* srcS = (const char*)(gS + (size_t)sb * N_HID + c * KC);
        unsigned int dstS = smem_u32 + SS_OFF + s * SS_STAGE_BYTES + sb * 272;
#pragma unroll
        for (int i = 0; i < 2; i++) {
            int cc = scb + i * 8;    // 16 x 16B = 256B row
            cpasync16(dstS + cc * 16, srcS + cc * 16);
        }
        asm volatile("cp.async.commit_group;\n" ::: "memory");
    };

    issue_stage(0, 0);
    issue_stage(1, 1);

#pragma unroll 1
    for (int c = 0; c < NCH; c++) {
        if (c + 1 < NCH)
            asm volatile("cp.async.wait_group 1;\n" ::: "memory");
        else
            asm volatile("cp.async.wait_group 0;\n" ::: "memory");
        __syncthreads();

        if (c + 2 < NCH) issue_stage(c + 2, (c + 2) % 3);

        const int s = c % 3;
        const __nv_bfloat16* ssb =
            (const __nv_bfloat16*)(smem_buf + SS_OFF + s * SS_STAGE_BYTES);
        const __nv_bfloat16* asb =
            (const __nv_bfloat16*)(smem_buf + AS_OFF + s * AS_STAGE_BYTES);

#pragma unroll
        for (int ks = 0; ks < KC / 16; ks++) {
            wmma::fragment<wmma::matrix_a, 16, 16, 16, __nv_bfloat16, wmma::row_major> af;
            wmma::load_matrix_sync(af, ssb + (wm * 16) * 136 + ks * 16, 136);
#pragma unroll
            for (int li = 0; li < 2; li++) {
                int l = 2 * g + li;
                wmma::fragment<wmma::matrix_b, 16, 16, 16, __nv_bfloat16, wmma::row_major> bfr;
                wmma::load_matrix_sync(bfr, asb + (l * 128 + ks * 16) * 40 + wn * 16, 40);
                wmma::mma_sync(acc[li], af, bfr, acc[li]);
            }
        }
    }

    // combine within group: group0 -> c0+c1, group1 -> c2+c3 (same element layout)
#pragma unroll
    for (int e = 0; e < acc[0].num_elements; e++)
        acc[0].x[e] = acc[0].x[e] + acc[1].x[e];

    float* CsA = (float*)(smem_buf + CSA_OFF);
    float* CsB = (float*)(smem_buf + CSB_OFF);
    float* Cdst = g ? CsB : CsA;
    __syncthreads();
    wmma::store_matrix_sync(Cdst + (wm * 16) * 36 + wn * 16, acc[0], 36,
                            wmma::mem_row_major);
    __syncthreads();

    // fused LIF epilogue: p = (c0+c1) + (c2+c3)  — same order as before
    __nv_bfloat16* gSn = &g_sbf[(t + 1) & 1][layer][0][0];
#pragma unroll
    for (int e = 0; e < 4; e++) {
        int flat = tid + e * 512;   // 0..2047
        int b = flat >> 5;
        int hl = flat & 31;
        int h = n0 + hl;
        float p = CsA[b * 36 + hl] + CsB[b * 36 + hl];
        float u = __ldcs(&g_U[layer][b * FRAMES + t][h]);
        size_t row_t = ((size_t)(layer * BATCH + b) * (FRAMES + 1) + t) * N_HID + h;
        float mprev = mems[row_t];
        float sprev = __bfloat162float(gS[(size_t)b * N_HID + h]);
        float y = tanhf(ALPHA * p + (1.0f - ALPHA) * u);
        float mn = DECAY * mprev - THR * (1.0f - sprev) + y;
        float sn = (mn > THR) ? 1.0f : 0.0f;
        mems[row_t + N_HID] = mn;
        __stcs(&spikes[row_t + N_HID], sn);
        gSn[(size_t)b * N_HID + h] = __float2bfloat16(sn);
    }
}

// ---------------------------------------------------------------------------
// Launch. Inputs: x, W_in1, A1, b1, W_in2, A2, b2, mem0_1, mem0_2
// ---------------------------------------------------------------------------
extern "C" void kernel_launch(void* const* d_in, const int* in_sizes, int n_in,
                              void* d_out, int out_size)
{
    const float* x      = (const float*)d_in[0];
    const float* W_in1  = (const float*)d_in[1];
    const float* A1     = (const float*)d_in[2];
    const float* b1     = (const float*)d_in[3];
    const float* W_in2  = (const float*)d_in[4];
    const float* A2     = (const float*)d_in[5];
    const float* b2     = (const float*)d_in[6];
    const float* mem0_1 = (const float*)d_in[7];
    const float* mem0_2 = (const float*)d_in[8];
    float* out = (float*)d_out;

    cudaFuncSetAttribute(step_mma_kernel,
                         cudaFuncAttributeMaxDynamicSharedMemorySize,
                         STEP_SMEM_BYTES);

    // A limb pack
    {
        size_t n = (size_t)2 * N_HID * N_HID;
        prep_A4_kernel<<<(unsigned)((n + 255) / 256), 256>>>(A1, A2);
    }
    // Feedforward drive (includes bias)
    {
        dim3 grid(N_HID / 128, (BATCH * FRAMES) / 128, 2);
        ff_kernel<<<grid, 256>>>(x, W_in1, b1, W_in2, b2);
    }
    // t=0 state
    {
        int total = 2 * BATCH * N_HID;
        init_kernel<<<(total + 255) / 256, 256>>>(mem0_1, mem0_2, out);
    }
    // Sequential time loop
    for (int t = 0; t < FRAMES; t++) {
        step_mma_kernel<<<128, 512, STEP_SMEM_BYTES>>>(out, t);
    }
}

// round 8
// speedup vs baseline: 1.9528x; 1.3276x over previous
#include <cuda_runtime.h>
#include <cuda_bf16.h>
#include <cuda_fp16.h>
#include <mma.h>
#include <math.h>
#include <cstdint>
#include <cstddef>

using namespace nvcuda;

#define BATCH 64
#define FRAMES 128
#define N_IN 512
#define N_HID 2048
#define ALPHA 0.5f
#define DECAY 0.5f
#define THR 0.5f

#define MEMS_ELEMS ((size_t)2 * BATCH * (FRAMES + 1) * N_HID)

// ---------------------------------------------------------------------------
// Device scratch
// ---------------------------------------------------------------------------
__device__ float g_U[2][BATCH * FRAMES][N_HID];  // x@W + bias
// A limbs (fp16, scaled 1 / 2^12 / 2^24), contiguous per (layer, ntile):
// [layer][ntile(64)][chunk(16)][limb(3)][kin(128)][col(32)]  (48MB)
__device__ __half g_Apack[(size_t)2 * 64 * 16 * 3 * 128 * 32];
// x limbs (fp16 scaled): [limb(3)][8192*512]  (24MB)
__device__ __half g_X[3][(size_t)BATCH * FRAMES * N_IN];
// W limbs (fp16 scaled): [limb(3)][2*512*2048]  (12MB)
__device__ __half g_W[3][(size_t)2 * N_IN * N_HID];
// fp16 spike scratch, ping-pong by parity: [par][layer][b][h]  (1MB)
__device__ __half g_sbf[2][2][BATCH][N_HID];

// 3-limb scaled fp16 split: a = h0 + h1*2^-12 + h2*2^-24 + r, |r| ~ 2^-36|a|
__device__ __forceinline__ void split3h(float a, __half& h0, __half& h1, __half& h2)
{
    float r = a;
    h0 = __float2half_rn(r);
    r -= __half2float(h0);
    h1 = __float2half_rn(r * 4096.0f);
    r -= __half2float(h1) * (1.0f / 4096.0f);
    h2 = __float2half_rn(r * 16777216.0f);
}

__global__ void prep_A3_kernel(const float* __restrict__ A1,
                               const float* __restrict__ A2)
{
    size_t per = (size_t)N_HID * N_HID;
    size_t idx = (size_t)blockIdx.x * blockDim.x + threadIdx.x;
    if (idx >= 2 * per) return;
    int layer = (int)(idx / per);
    size_t rem = idx % per;
    int k = (int)(rem / N_HID);
    int n = (int)(rem % N_HID);
    float a = (layer ? A2 : A1)[rem];

    int nt = n >> 5, col = n & 31;
    int chunk = k >> 7, kin = k & 127;
    size_t base = ((((size_t)(layer * 64 + nt) * 16 + chunk) * 3) * 128 + kin) * 32 + col;

    __half h0, h1, h2;
    split3h(a, h0, h1, h2);
    g_Apack[base] = h0;
    g_Apack[base + (size_t)128 * 32] = h1;
    g_Apack[base + (size_t)2 * 128 * 32] = h2;
}

__global__ void prep_x3_kernel(const float* __restrict__ x)
{
    size_t total = (size_t)BATCH * FRAMES * N_IN;
    size_t idx = (size_t)blockIdx.x * blockDim.x + threadIdx.x;
    if (idx >= total) return;
    __half h0, h1, h2;
    split3h(x[idx], h0, h1, h2);
    g_X[0][idx] = h0; g_X[1][idx] = h1; g_X[2][idx] = h2;
}

__global__ void prep_W3_kernel(const float* __restrict__ W1,
                               const float* __restrict__ W2)
{
    size_t per = (size_t)N_IN * N_HID;
    size_t idx = (size_t)blockIdx.x * blockDim.x + threadIdx.x;
    if (idx >= 2 * per) return;
    float a = (idx < per) ? W1[idx] : W2[idx - per];
    __half h0, h1, h2;
    split3h(a, h0, h1, h2);
    g_W[0][idx] = h0; g_W[1][idx] = h1; g_W[2][idx] = h2;
}

// ---------------------------------------------------------------------------
// Feedforward GEMM via fp16 wmma, 6 limb-product passes (i+j<=2), per-pass
// scale 2^-12(i+j) applied when folding into the fp32 running total.
// CTA tile 128(m) x 64(n), 256 threads / 8 warps, warp = 2x2 16-tiles.
// grid: (2048/64, 8192/128, 2 layers)
// ---------------------------------------------------------------------------
__global__ void __launch_bounds__(256) ff_wmma_kernel(
    const float* __restrict__ b1, const float* __restrict__ b2)
{
    const int n0 = blockIdx.x * 64;
    const int m0 = blockIdx.y * 128;
    const int layer = blockIdx.z;

    __shared__ __half Xs[128][40];   // [m][k], kc=32, stride 40
    __shared__ __half Ws[32][72];    // [k][n], stride 72

    const int tid = threadIdx.x;
    const int wid = tid >> 5;
    const int wm = wid >> 1;        // 0..3 -> m-tiles 2wm, 2wm+1
    const int wn = (wid & 1) * 2;   // n-tiles wn, wn+1

    wmma::fragment<wmma::accumulator, 16, 16, 16, float> ctot[2][2];
#pragma unroll
    for (int i = 0; i < 2; i++)
#pragma unroll
        for (int j = 0; j < 2; j++) wmma::fill_fragment(ctot[i][j], 0.0f);

    const int PI[6] = {0, 0, 1, 0, 2, 1};
    const int PJ[6] = {0, 1, 0, 2, 0, 1};
    const float PS[6] = {1.0f, 0x1p-12f, 0x1p-12f, 0x1p-24f, 0x1p-24f, 0x1p-24f};

#pragma unroll 1
    for (int p = 0; p < 6; p++) {
        const __half* __restrict__ Xsrc = &g_X[PI[p]][0];
        const __half* __restrict__ Wsrc = &g_W[PJ[p]][(size_t)layer * N_IN * N_HID];

        wmma::fragment<wmma::accumulator, 16, 16, 16, float> acc[2][2];
#pragma unroll
        for (int i = 0; i < 2; i++)
#pragma unroll
            for (int j = 0; j < 2; j++) wmma::fill_fragment(acc[i][j], 0.0f);

#pragma unroll 1
        for (int k0 = 0; k0 < N_IN; k0 += 32) {
            // stage X tile: 128 x 32 fp16 (512 x 16B; 2 per thread)
#pragma unroll
            for (int i = 0; i < 2; i++) {
                int idx = tid + i * 256;
                int row = idx >> 2;
                int q = (idx & 3) * 8;
                *(uint4*)&Xs[row][q] =
                    *(const uint4*)&Xsrc[(size_t)(m0 + row) * N_IN + k0 + q];
            }
            // stage W tile: 32 x 64 fp16 (256 x 16B)
            {
                int row = tid >> 3;
                int cc = (tid & 7) * 8;
                *(uint4*)&Ws[row][cc] =
                    *(const uint4*)&Wsrc[(size_t)(k0 + row) * N_HID + n0 + cc];
            }
            __syncthreads();

#pragma unroll
            for (int ks = 0; ks < 2; ks++) {
                wmma::fragment<wmma::matrix_a, 16, 16, 16, __half, wmma::row_major> af[2];
                wmma::fragment<wmma::matrix_b, 16, 16, 16, __half, wmma::row_major> bf[2];
#pragma unroll
                for (int i = 0; i < 2; i++)
                    wmma::load_matrix_sync(af[i], &Xs[(2 * wm + i) * 16][ks * 16], 40);
#pragma unroll
                for (int j = 0; j < 2; j++)
                    wmma::load_matrix_sync(bf[j], &Ws[ks * 16][(wn + j) * 16], 72);
#pragma unroll
                for (int i = 0; i < 2; i++)
#pragma unroll
                    for (int j = 0; j < 2; j++)
                        wmma::mma_sync(acc[i][j], af[i], bf[j], acc[i][j]);
            }
            __syncthreads();
        }

        // fold scaled pass result into total
        const float sc = PS[p];
#pragma unroll
        for (int i = 0; i < 2; i++)
#pragma unroll
            for (int j = 0; j < 2; j++)
#pragma unroll
                for (int e = 0; e < ctot[0][0].num_elements; e++)
                    ctot[i][j].x[e] += acc[i][j].x[e] * sc;
    }

    // epilogue: add bias, write U
    const float* __restrict__ bias = layer ? b2 : b1;
    __shared__ float Cs[128][72];
#pragma unroll
    for (int i = 0; i < 2; i++)
#pragma unroll
        for (int j = 0; j < 2; j++)
            wmma::store_matrix_sync(&Cs[(2 * wm + i) * 16][(wn + j) * 16],
                                    ctot[i][j], 72, wmma::mem_row_major);
    __syncthreads();
    float* __restrict__ U = &g_U[layer][0][0];
#pragma unroll
    for (int e = 0; e < 32; e++) {
        int flat = tid + e * 256;        // 0..8191 = 128 x 64
        int row = flat >> 6;
        int col = flat & 63;
        U[(size_t)(m0 + row) * N_HID + n0 + col] = Cs[row][col] + bias[n0 + col];
    }
}

// ---------------------------------------------------------------------------
// Init t=0 state (fp32 outputs + fp16 scratch parity 0)
// ---------------------------------------------------------------------------
__global__ void init_kernel(const float* __restrict__ mem0_1,
                            const float* __restrict__ mem0_2,
                            float* __restrict__ out)
{
    float* mems = out;
    float* spikes = out + MEMS_ELEMS;
    size_t idx = (size_t)blockIdx.x * blockDim.x + threadIdx.x;
    size_t total = (size_t)2 * BATCH * N_HID;
    if (idx >= total) return;
    int l = (int)(idx / ((size_t)BATCH * N_HID));
    size_t rem = idx % ((size_t)BATCH * N_HID);
    int b = (int)(rem / N_HID);
    int h = (int)(rem % N_HID);
    const float* m0 = l ? mem0_2 : mem0_1;
    size_t o = ((size_t)(l * BATCH + b) * (FRAMES + 1)) * N_HID + h;
    mems[o] = m0[(size_t)b * N_HID + h];
    spikes[o] = 0.f;
    g_sbf[0][l][b][h] = __float2half(0.f);
}

// ---------------------------------------------------------------------------
// Fused pipelined step. Grid 128 = 2 layers x 64 coltiles(32). Block 512.
// 3-limb fp16 A; 16 warps: group0 (warps 0-7) limbs {0,1}, group1 limb {2}.
// KC=128, 3-stage cp.async pipeline; A loads tagged L2::evict_last.
// ---------------------------------------------------------------------------
#define KC 128
#define NCH (N_HID / KC)                   // 16 chunks
#define SS_STAGE_BYTES (64 * 272)          // 64 rows x 136 fp16
#define AS_STAGE_BYTES (384 * 80)          // 3 limbs x 128 k x 40 fp16
#define SS_OFF 0
#define AS_OFF (3 * SS_STAGE_BYTES)                 // 52224
#define CSA_OFF (AS_OFF + 3 * AS_STAGE_BYTES)       // 144384
#define CSB_OFF (CSA_OFF + 64 * 36 * 4)             // 153600
#define STEP_SMEM_BYTES (CSB_OFF + 64 * 36 * 4)     // 162816

__device__ __forceinline__ void cpasync16(unsigned int dst, const void* src)
{
    asm volatile("cp.async.cg.shared.global [%0], [%1], 16;\n" ::"r"(dst), "l"(src));
}
__device__ __forceinline__ void cpasync16_el(unsigned int dst, const void* src,
                                             unsigned long long pol)
{
    asm volatile("cp.async.cg.shared.global.L2::cache_hint [%0], [%1], 16, %2;\n"
                 ::"r"(dst), "l"(src), "l"(pol));
}

extern __shared__ char smem_buf[];

__global__ void __launch_bounds__(512) step_mma_kernel(float* __restrict__ out, int t)
{
    const int bx = blockIdx.x;
    const int layer = bx >> 6;
    const int nt = bx & 63;
    const int n0 = nt * 32;

    const int tid = threadIdx.x;
    const int wid = tid >> 5;
    const int g  = wid >> 3;       // 0: limbs {0,1}; 1: limb {2}
    const int w8 = wid & 7;
    const int wm = w8 >> 1;        // 0..3 m-tile
    const int wn = w8 & 1;         // 0..1 n-tile

    float* mems = out;
    float* spikes = out + MEMS_ELEMS;

    const __half* __restrict__ Abase =
        g_Apack + (size_t)(layer * 64 + nt) * (16 * 3 * 128 * 32);
    const __half* __restrict__ gS = &g_sbf[t & 1][layer][0][0];

    const unsigned int smem_u32 = (unsigned int)__cvta_generic_to_shared(smem_buf);

    unsigned long long pol;
    asm("createpolicy.fractional.L2::evict_last.b64 %0, 1.0;" : "=l"(pol));

    wmma::fragment<wmma::accumulator, 16, 16, 16, float> acc[2];
#pragma unroll
    for (int i = 0; i < 2; i++) wmma::fill_fragment(acc[i], 0.0f);

    // per-thread copy maps (512 threads)
    const int aj = tid & 3;          // 16B chunk within 64B A row
    const int ar0 = tid >> 2;        // A row base (0..127)
    const int sb = tid >> 3;         // spike row (0..63)
    const int scb = tid & 7;         // spike 16B chunk base

    auto issue_stage = [&](int c, int s) {
        const char* srcA = (const char*)(Abase + (size_t)c * (3 * 128 * 32));
        unsigned int dstA = smem_u32 + AS_OFF + s * AS_STAGE_BYTES;
#pragma unroll
        for (int i = 0; i < 3; i++) {
            int r = ar0 + i * 128;   // 0..383 (A (limb,kin) row of 64B)
            cpasync16_el(dstA + r * 80 + aj * 16, srcA + r * 64 + aj * 16, pol);
        }
        const char* srcS = (const char*)(gS + (size_t)sb * N_HID + c * KC);
        unsigned int dstS = smem_u32 + SS_OFF + s * SS_STAGE_BYTES + sb * 272;
#pragma unroll
        for (int i = 0; i < 2; i++) {
            int cc = scb + i * 8;    // 16 x 16B = 256B row
            cpasync16(dstS + cc * 16, srcS + cc * 16);
        }
        asm volatile("cp.async.commit_group;\n" ::: "memory");
    };

    issue_stage(0, 0);
    issue_stage(1, 1);

#pragma unroll 1
    for (int c = 0; c < NCH; c++) {
        if (c + 1 < NCH)
            asm volatile("cp.async.wait_group 1;\n" ::: "memory");
        else
            asm volatile("cp.async.wait_group 0;\n" ::: "memory");
        __syncthreads();

        if (c + 2 < NCH) issue_stage(c + 2, (c + 2) % 3);

        const int s = c % 3;
        const __half* ssb = (const __half*)(smem_buf + SS_OFF + s * SS_STAGE_BYTES);
        const __half* asb = (const __half*)(smem_buf + AS_OFF + s * AS_STAGE_BYTES);

#pragma unroll
        for (int ks = 0; ks < KC / 16; ks++) {
            wmma::fragment<wmma::matrix_a, 16, 16, 16, __half, wmma::row_major> af;
            wmma::load_matrix_sync(af, ssb + (wm * 16) * 136 + ks * 16, 136);
            if (g == 0) {
#pragma unroll
                for (int li = 0; li < 2; li++) {
                    wmma::fragment<wmma::matrix_b, 16, 16, 16, __half, wmma::row_major> bfr;
                    wmma::load_matrix_sync(bfr, asb + (li * 128 + ks * 16) * 40 + wn * 16, 40);
                    wmma::mma_sync(acc[li], af, bfr, acc[li]);
                }
            } else {
                wmma::fragment<wmma::matrix_b, 16, 16, 16, __half, wmma::row_major> bfr;
                wmma::load_matrix_sync(bfr, asb + (2 * 128 + ks * 16) * 40 + wn * 16, 40);
                wmma::mma_sync(acc[0], af, bfr, acc[0]);
            }
        }
    }

    // combine with limb scales: group0 -> c0 + c1*2^-12, group1 -> c2*2^-24
#pragma unroll
    for (int e = 0; e < acc[0].num_elements; e++)
        acc[0].x[e] = g ? acc[0].x[e] * 0x1p-24f
                        : acc[0].x[e] + acc[1].x[e] * 0x1p-12f;

    float* CsA = (float*)(smem_buf + CSA_OFF);
    float* CsB = (float*)(smem_buf + CSB_OFF);
    float* Cdst = g ? CsB : CsA;
    __syncthreads();
    wmma::store_matrix_sync(Cdst + (wm * 16) * 36 + wn * 16, acc[0], 36,
                            wmma::mem_row_major);
    __syncthreads();

    // fused LIF epilogue: p = (c0 + c1*2^-12) + c2*2^-24
    __half* gSn = &g_sbf[(t + 1) & 1][layer][0][0];
#pragma unroll
    for (int e = 0; e < 4; e++) {
        int flat = tid + e * 512;   // 0..2047
        int b = flat >> 5;
        int hl = flat & 31;
        int h = n0 + hl;
        float p = CsA[b * 36 + hl] + CsB[b * 36 + hl];
        float u = __ldcs(&g_U[layer][b * FRAMES + t][h]);
        size_t row_t = ((size_t)(layer * BATCH + b) * (FRAMES + 1) + t) * N_HID + h;
        float mprev = mems[row_t];
        float sprev = __half2float(gS[(size_t)b * N_HID + h]);
        float y = tanhf(ALPHA * p + (1.0f - ALPHA) * u);
        float mn = DECAY * mprev - THR * (1.0f - sprev) + y;
        float sn = (mn > THR) ? 1.0f : 0.0f;
        mems[row_t + N_HID] = mn;
        __stcs(&spikes[row_t + N_HID], sn);
        gSn[(size_t)b * N_HID + h] = __float2half(sn);
    }
}

// ---------------------------------------------------------------------------
// Launch. Inputs: x, W_in1, A1, b1, W_in2, A2, b2, mem0_1, mem0_2
// ---------------------------------------------------------------------------
extern "C" void kernel_launch(void* const* d_in, const int* in_sizes, int n_in,
                              void* d_out, int out_size)
{
    const float* x      = (const float*)d_in[0];
    const float* W_in1  = (const float*)d_in[1];
    const float* A1     = (const float*)d_in[2];
    const float* b1     = (const float*)d_in[3];
    const float* W_in2  = (const float*)d_in[4];
    const float* A2     = (const float*)d_in[5];
    const float* b2     = (const float*)d_in[6];
    const float* mem0_1 = (const float*)d_in[7];
    const float* mem0_2 = (const float*)d_in[8];
    float* out = (float*)d_out;

    cudaFuncSetAttribute(step_mma_kernel,
                         cudaFuncAttributeMaxDynamicSharedMemorySize,
                         STEP_SMEM_BYTES);

    // limb packs
    {
        size_t n = (size_t)2 * N_HID * N_HID;
        prep_A3_kernel<<<(unsigned)((n + 255) / 256), 256>>>(A1, A2);
    }
    {
        size_t n = (size_t)BATCH * FRAMES * N_IN;
        prep_x3_kernel<<<(unsigned)((n + 255) / 256), 256>>>(x);
    }
    {
        size_t n = (size_t)2 * N_IN * N_HID;
        prep_W3_kernel<<<(unsigned)((n + 255) / 256), 256>>>(W_in1, W_in2);
    }

    // Feedforward drive on tensor cores (includes bias)
    {
        dim3 grid(N_HID / 64, (BATCH * FRAMES) / 128, 2);
        ff_wmma_kernel<<<grid, 256>>>(b1, b2);
    }

    // t=0 state
    {
        int total = 2 * BATCH * N_HID;
        init_kernel<<<(total + 255) / 256, 256>>>(mem0_1, mem0_2, out);
    }

    // Sequential time loop
    for (int t = 0; t < FRAMES; t++) {
        step_mma_kernel<<<128, 512, STEP_SMEM_BYTES>>>(out, t);
    }
}